// round 7
// baseline (speedup 1.0000x reference)
#include <cuda_runtime.h>
#include <cuda_bf16.h>

// dynFilter: out[b,1,h,w] = tanh( sum_{c,ky,kx} x[b,c,h+ky-2,w+kx-2] * filt[b, c*25+ky*5+kx, h, w] )
// x [8,4,256,256] f32, filt [8,100,256,256] f32, out [8,1,256,256] f32.
// HBM-bound, ~210 MB compulsory DRAM traffic (floor ~26us).
// History: R2 39.7us (batch-5 loads), R3 FAIL 49us (reg cut killed pipelining),
// R6 38.0us @ DRAM 72%, occ 38.6% == theoretical cap. Warp count maxed;
// remaining gap = per-warp scoreboard dead time between load batches.
// R7: explicit 1-deep software pipeline over the 20 (c,ky) groups — prefetch
// group g+1's 5 filt LDG.128 before consuming group g. Guarantees 5-10 loads
// in flight per warp continuously, by dataflow rather than compiler luck.

#define KK 5
#define PADK 2
#define CC 4
#define HH 256
#define WW 256
#define TILE_H 4
#define TILE_W 128
#define NROWS (TILE_H + 2 * PADK)        // 8 halo rows
#define NCOLS (TILE_W + 2 * PADK)        // 132 halo cols
#define NCOLS_PAD 136                    // 16B-aligned row stride
#define NGROUPS (CC * KK)                // 20 (c,ky) groups

__device__ __forceinline__ float tanh_approx(float v) {
    float r;
    asm("tanh.approx.f32 %0, %1;" : "=f"(r) : "f"(v));
    return r;
}

__global__ __launch_bounds__(128, 7)
void dynfilter_kernel(const float* __restrict__ x,
                      const float* __restrict__ filt,
                      float* __restrict__ out)
{
    const int b     = blockIdx.z;
    const int whalf = blockIdx.y;            // 0..1
    const int h0    = blockIdx.x * TILE_H;   // tile row base
    const int w0    = whalf * TILE_W;        // tile col base
    const int tid   = threadIdx.x;

    __shared__ __align__(16) float xs[CC][NROWS][NCOLS_PAD];

    // Cooperative halo load: rows h0-2..h0+5, cols w0-2..w0+129 (zero pad OOB).
    #pragma unroll
    for (int it = 0; it < (CC * NROWS * NCOLS + 127) / 128; ++it) {
        int idx = it * 128 + tid;
        if (idx < CC * NROWS * NCOLS) {
            int c   = idx / (NROWS * NCOLS);
            int rem = idx % (NROWS * NCOLS);
            int r   = rem / NCOLS;
            int col = rem % NCOLS;
            int gr = h0 - PADK + r;
            int gc = w0 - PADK + col;
            float v = 0.0f;
            if (gr >= 0 && gr < HH && gc >= 0 && gc < WW)
                v = x[(((b * CC) + c) * HH + gr) * WW + gc];
            xs[c][r][col] = v;
        }
    }
    __syncthreads();

    const int hr = tid >> 5;       // 0..3 row within tile
    const int q  = tid & 31;       // 0..31 float4 column within tile
    const int h  = h0 + hr;
    const int wl = q << 2;         // local smem col of window start (w-2 incl halo)

    float acc0 = 0.f, acc1 = 0.f, acc2 = 0.f, acc3 = 0.f;

    const long plane = (long)(HH * WW / 4);  // 16384 float4 per plane
    // Base pointer for (b, h, this thread's float4 column), plane p = 0.
    const float4* __restrict__ fp =
        (const float4*)filt +
        (((long)b * (CC * KK * KK) * HH + h) * (WW / 4) + (whalf * 32 + q));

    // Prime the pipeline: group 0's five filt loads.
    float4 f0 = __ldcs(fp + 0 * plane);
    float4 f1 = __ldcs(fp + 1 * plane);
    float4 f2 = __ldcs(fp + 2 * plane);
    float4 f3 = __ldcs(fp + 3 * plane);
    float4 f4 = __ldcs(fp + 4 * plane);

    #pragma unroll
    for (int g = 0; g < NGROUPS; ++g) {
        // Prefetch group g+1 before consuming group g.
        float4 n0, n1, n2, n3, n4;
        if (g + 1 < NGROUPS) {
            const float4* np = fp + (long)(g + 1) * KK * plane;
            n0 = __ldcs(np + 0 * plane);
            n1 = __ldcs(np + 1 * plane);
            n2 = __ldcs(np + 2 * plane);
            n3 = __ldcs(np + 3 * plane);
            n4 = __ldcs(np + 4 * plane);
        }

        // Window row for this group: 8 floats via two conflict-free LDS.128.
        const int c  = g / KK;
        const int ky = g % KK;
        const float4 a  = *(const float4*)&xs[c][hr + ky][wl];
        const float4 bb = *(const float4*)&xs[c][hr + ky][wl + 4];
        const float xr0 = a.x,  xr1 = a.y,  xr2 = a.z,  xr3 = a.w;
        const float xr4 = bb.x, xr5 = bb.y, xr6 = bb.z, xr7 = bb.w;

        // kx = 0..4; acc_i += xr[kx+i] * f[kx].lane_i
        acc0 = fmaf(xr0, f0.x, acc0); acc1 = fmaf(xr1, f0.y, acc1);
        acc2 = fmaf(xr2, f0.z, acc2); acc3 = fmaf(xr3, f0.w, acc3);

        acc0 = fmaf(xr1, f1.x, acc0); acc1 = fmaf(xr2, f1.y, acc1);
        acc2 = fmaf(xr3, f1.z, acc2); acc3 = fmaf(xr4, f1.w, acc3);

        acc0 = fmaf(xr2, f2.x, acc0); acc1 = fmaf(xr3, f2.y, acc1);
        acc2 = fmaf(xr4, f2.z, acc2); acc3 = fmaf(xr5, f2.w, acc3);

        acc0 = fmaf(xr3, f3.x, acc0); acc1 = fmaf(xr4, f3.y, acc1);
        acc2 = fmaf(xr5, f3.z, acc2); acc3 = fmaf(xr6, f3.w, acc3);

        acc0 = fmaf(xr4, f4.x, acc0); acc1 = fmaf(xr5, f4.y, acc1);
        acc2 = fmaf(xr6, f4.z, acc2); acc3 = fmaf(xr7, f4.w, acc3);

        // Rotate buffers (renamed away by full unroll).
        f0 = n0; f1 = n1; f2 = n2; f3 = n3; f4 = n4;
    }

    float4 o;
    o.x = tanh_approx(acc0);
    o.y = tanh_approx(acc1);
    o.z = tanh_approx(acc2);
    o.w = tanh_approx(acc3);
    ((float4*)out)[((long)b * HH + h) * (WW / 4) + whalf * 32 + q] = o;
}

extern "C" void kernel_launch(void* const* d_in, const int* in_sizes, int n_in,
                              void* d_out, int out_size)
{
    const float* x    = (const float*)d_in[0];   // [8,4,256,256]
    const float* filt = (const float*)d_in[1];   // [8,100,256,256]
    float* out        = (float*)d_out;           // [8,1,256,256]

    dim3 grid(HH / TILE_H, WW / TILE_W, 8);   // 64 x 2 x 8 = 1024 CTAs
    dim3 block(128);
    dynfilter_kernel<<<grid, block>>>(x, filt, out);
}